// round 8
// baseline (speedup 1.0000x reference)
#include <cuda_runtime.h>

#define B_ 2
#define T_ 2048
#define C_ 1024
#define H_ 16
#define D_ 64
#define MROWS (B_ * T_)   // 4096

// Scratch (allocation-free rule: __device__ globals). All hold TF32-grid values.
__device__ float g_q[B_ * H_ * T_ * D_];
__device__ float g_k[B_ * H_ * T_ * D_];
__device__ float g_v[B_ * H_ * T_ * D_];
__device__ float g_y[MROWS * C_];          // flash output, pre-rounded at store
__device__ float g_x[MROWS * C_];          // x, pre-rounded
__device__ float g_wa[C_ * 3 * C_];        // W_attn, pre-rounded
__device__ float g_wp[C_ * C_];            // W_proj, pre-rounded

// ---------------------------------------------------------------------------
// TF32 / async-copy helpers
// ---------------------------------------------------------------------------
__device__ __forceinline__ unsigned f2tf(float x) {
    unsigned r;
    asm("cvt.rna.tf32.f32 %0, %1;" : "=r"(r) : "f"(x));
    return r;
}
__device__ __forceinline__ float f2tff(float x) { return __uint_as_float(f2tf(x)); }

__device__ __forceinline__ void mma8(float* c, const unsigned* a, const unsigned* b) {
    asm volatile(
        "mma.sync.aligned.m16n8k8.row.col.f32.tf32.tf32.f32 "
        "{%0,%1,%2,%3},{%4,%5,%6,%7},{%8,%9},{%0,%1,%2,%3};\n"
        : "+f"(c[0]), "+f"(c[1]), "+f"(c[2]), "+f"(c[3])
        : "r"(a[0]), "r"(a[1]), "r"(a[2]), "r"(a[3]),
          "r"(b[0]), "r"(b[1]));
}

__device__ __forceinline__ void cpa16(void* smem, const void* gmem) {
    unsigned saddr = (unsigned)__cvta_generic_to_shared(smem);
    asm volatile("cp.async.cg.shared.global [%0], [%1], 16;" :: "r"(saddr), "l"(gmem));
}
#define CP_COMMIT() asm volatile("cp.async.commit_group;")
#define CP_WAIT0()  asm volatile("cp.async.wait_group 0;")

// ---------------------------------------------------------------------------
// One-time TF32 pre-rounding pass (float4 vectorized, grid-stride)
// ---------------------------------------------------------------------------
__global__ void round_kernel(const float4* __restrict__ src,
                             float4* __restrict__ dst, int n4)
{
    for (int i = blockIdx.x * blockDim.x + threadIdx.x; i < n4;
         i += gridDim.x * blockDim.x) {
        float4 v = src[i];
        v.x = f2tff(v.x); v.y = f2tff(v.y);
        v.z = f2tff(v.z); v.w = f2tff(v.w);
        dst[i] = v;
    }
}

// ---------------------------------------------------------------------------
// Paired scatter for QKV epilogue: row-major [4096, 3072] -> Q/K/V [B,H,T,D]
// c0 is even, so (c0, c0+1) share head/tensor and d, d+1 are adjacent:
// one float2 (STG.64) store. Values rounded to the TF32 grid HERE.
// ---------------------------------------------------------------------------
__device__ __forceinline__ void store_qkv2(int r, int c, float v0, float v1) {
    int which = c >> 10;       // 0=q 1=k 2=v
    int cc = c & 1023;
    int h = cc >> 6;
    int d = cc & 63;
    int b = r >> 11;           // / T_
    int t = r & 2047;
    float* dst = (which == 0) ? g_q : ((which == 1) ? g_k : g_v);
    float2 p;
    p.x = f2tff(v0);
    p.y = f2tff(v1);
    *(float2*)&dst[(((b * H_ + h) * T_ + t) << 6) + d] = p;
}

// ---------------------------------------------------------------------------
// TF32 GEMM, BK=32, 2-stage cp.async pipeline: out[M,N] = A[M,K]@W[K,N]+bias
// Operands PRE-ROUNDED to the TF32 grid in gmem -> mainloop has NO cvts.
// mode 0: A = g_x,  W = g_wa, scatter-epilogue into g_q/g_k/g_v (QKV)
// mode 1: A = g_y,  W = g_wp, plain row-major epilogue into out (proj)
// BM=128, BN=128, BK=32, 256 threads (warps 4x2, warp tile 32x64)
// Dynamic smem: 2 x (A 128x36 + B 32x136) floats = 71,680 B
// ---------------------------------------------------------------------------
#define GA_STRIDE 36    // A-frag banks (4g+tg)%32 bijective; row base 144B (16-aligned)
#define GB_STRIDE 136   // B-frag banks (8tg+g)%32 bijective; row base 544B (16-aligned)
#define GA_FLOATS (128 * GA_STRIDE)   // per stage: 4608
#define GB_FLOATS (32 * GB_STRIDE)    // per stage: 4352
#define GEMM_SMEM_BYTES ((2 * (GA_FLOATS + GB_FLOATS)) * 4)   // 71680

__global__ __launch_bounds__(256, 2)
void gemm_kernel(const float* __restrict__ bias, float* __restrict__ out,
                 int M, int N, int K, int mode)
{
    extern __shared__ __align__(16) float gsm[];
    float* Asm = gsm;                       // [2][128][GA_STRIDE]
    float* Bsm = gsm + 2 * GA_FLOATS;       // [2][32][GB_STRIDE]
#define AS(s, r, c) Asm[((s) * 128 + (r)) * GA_STRIDE + (c)]
#define BS(s, k, n) Bsm[((s) * 32 + (k)) * GB_STRIDE + (n)]

    const float* Ap = (mode == 1) ? g_y : g_x;
    const float* W  = (mode == 1) ? g_wp : g_wa;

    int tid = threadIdx.x;
    int warp = tid >> 5, lane = tid & 31;
    int g = lane >> 2, tg = lane & 3;
    int wm = warp >> 1, wn = warp & 1;
    int bm = blockIdx.y * 128, bn = blockIdx.x * 128;

    // staging coords: A 128x32 = 1024 float4 (4/thread), B 32x128 = 1024 float4
    int a_row = tid >> 3,  a_col = (tid & 7) * 4;    // rows 0..31 (+32/pass)
    int b_kr  = tid >> 5,  b_nq  = (tid & 31) * 4;   // k-rows 0..7 (+8/pass)

    float acc[2][8][4];
    #pragma unroll
    for (int mt = 0; mt < 2; mt++)
        #pragma unroll
        for (int nt = 0; nt < 8; nt++)
            #pragma unroll
            for (int i = 0; i < 4; i++) acc[mt][nt][i] = 0.0f;

    const int nst = K >> 5;   // K/32 stages (=32 here)

    // prologue: prefetch stage 0 into buffer 0
    #pragma unroll
    for (int p = 0; p < 4; p++) {
        int ar = a_row + p * 32;
        cpa16(&AS(0, ar, a_col), &Ap[(bm + ar) * K + a_col]);
        int kr = b_kr + p * 8;
        cpa16(&BS(0, kr, b_nq),  &W[kr * N + bn + b_nq]);
    }
    CP_COMMIT();

    for (int it = 0; it < nst; it++) {
        int s = it & 1;
        CP_WAIT0();
        __syncthreads();   // stage `it` resident; buf s^1 readers (iter it-1) done

        if (it + 1 < nst) {
            int k0 = (it + 1) << 5;
            int d = s ^ 1;
            #pragma unroll
            for (int p = 0; p < 4; p++) {
                int ar = a_row + p * 32;
                cpa16(&AS(d, ar, a_col), &Ap[(bm + ar) * K + k0 + a_col]);
                int kr = b_kr + p * 8;
                cpa16(&BS(d, kr, b_nq),  &W[(k0 + kr) * N + bn + b_nq]);
            }
            CP_COMMIT();
        }

        #pragma unroll
        for (int kk = 0; kk < 4; kk++) {
            unsigned af[2][4], bf[8][2];
            #pragma unroll
            for (int mt = 0; mt < 2; mt++) {
                int r = wm * 32 + mt * 16 + g;
                af[mt][0] = __float_as_uint(AS(s, r,     kk * 8 + tg    ));
                af[mt][1] = __float_as_uint(AS(s, r + 8, kk * 8 + tg    ));
                af[mt][2] = __float_as_uint(AS(s, r,     kk * 8 + tg + 4));
                af[mt][3] = __float_as_uint(AS(s, r + 8, kk * 8 + tg + 4));
            }
            #pragma unroll
            for (int nt = 0; nt < 8; nt++) {
                int c = wn * 64 + nt * 8 + g;
                bf[nt][0] = __float_as_uint(BS(s, kk * 8 + tg,     c));
                bf[nt][1] = __float_as_uint(BS(s, kk * 8 + tg + 4, c));
            }
            #pragma unroll
            for (int mt = 0; mt < 2; mt++)
                #pragma unroll
                for (int nt = 0; nt < 8; nt++)
                    mma8(acc[mt][nt], af[mt], bf[nt]);
        }
        // next iteration's top __syncthreads (after CP_WAIT0) protects buf reuse
    }

    // epilogue (paired float2 stores; c0 even)
    #pragma unroll
    for (int mt = 0; mt < 2; mt++) {
        int r0 = bm + wm * 32 + mt * 16 + g;
        #pragma unroll
        for (int nt = 0; nt < 8; nt++) {
            int c0 = bn + wn * 64 + nt * 8 + 2 * tg;
            float bb0 = bias[c0], bb1 = bias[c0 + 1];
            #pragma unroll
            for (int half = 0; half < 2; half++) {
                int r = r0 + half * 8;
                float v0 = acc[mt][nt][half * 2 + 0] + bb0;
                float v1 = acc[mt][nt][half * 2 + 1] + bb1;
                if (mode == 0) {
                    store_qkv2(r, c0, v0, v1);
                } else {
                    float2 p; p.x = v0; p.y = v1;
                    *(float2*)&out[r * N + c0] = p;
                }
            }
        }
    }
#undef AS
#undef BS
}

// ---------------------------------------------------------------------------
// Flash attention v2: CTA per (qtile=128 rows, h, b). 8 warps, 16 q-rows each.
// Double-buffered cp.async K/V staging (dynamic smem, 71,680 B).
// K/V/Q are pre-rounded to TF32 in gmem -> smem loads feed mma with NO cvt.
// P refragmented C->A via intra-quad shuffles (no smem bounce, 1 sync/iter).
// Output g_y stored pre-rounded (proj GEMM consumes it cvt-free).
// LPT scheduling: heaviest q-tiles (largest qt, work ~ 2qt+2) get the LOWEST
// blockIdx.x so they start in wave 1; short tiles backfill the tail.
// ---------------------------------------------------------------------------
#define KS_STRIDE 68   // S B-frag bank = 4g+tg (mod 32): bijective, conflict-free
#define VS_STRIDE 72   // PV B-frag bank = 8tg+g (mod 32): bijective, conflict-free
#define KS_FLOATS (64 * KS_STRIDE)            // 4352
#define VS_FLOATS (64 * VS_STRIDE)            // 4608
#define FLASH_SMEM_BYTES ((2 * (KS_FLOATS + VS_FLOATS)) * 4)   // 71680

__global__ __launch_bounds__(256)
void flash_kernel()
{
    extern __shared__ __align__(16) float smem[];
    // layout: Ks[0], Ks[1], Vs[0], Vs[1]
    float* KsBuf[2] = { smem,                smem + KS_FLOATS };
    float* VsBuf[2] = { smem + 2*KS_FLOATS,  smem + 2*KS_FLOATS + VS_FLOATS };

    int b = blockIdx.z, h = blockIdx.y;
    int qt = gridDim.x - 1 - blockIdx.x;   // longest-processing-time-first
    int tid = threadIdx.x, w = tid >> 5, lane = tid & 31;
    int g = lane >> 2, tg = lane & 3;
    int qbase = qt * 128;

    const float* qptr = g_q + (((b * H_ + h) * T_) << 6);
    const float* kptr = g_k + (((b * H_ + h) * T_) << 6);
    const float* vptr = g_v + (((b * H_ + h) * T_) << 6);

    // per-thread staging coords: 4 float4 per tile (256 thr x 4 x 16B = 16KB)
    int st_row = tid >> 4;            // 0..15 (+16 per pass)
    int st_col = (tid & 15) * 4;

    // Q fragments, pre-scaled by 1/sqrt(D)=0.125 (exact exponent shift:
    // commutes with TF32 rounding; q values already on the TF32 grid)
    unsigned aq[8][4];
    {
        int r0 = qbase + w * 16 + g;
        #pragma unroll
        for (int ks = 0; ks < 8; ks++) {
            aq[ks][0] = __float_as_uint(0.125f * qptr[ r0      * 64 + ks * 8 + tg    ]);
            aq[ks][1] = __float_as_uint(0.125f * qptr[(r0 + 8) * 64 + ks * 8 + tg    ]);
            aq[ks][2] = __float_as_uint(0.125f * qptr[ r0      * 64 + ks * 8 + tg + 4]);
            aq[ks][3] = __float_as_uint(0.125f * qptr[(r0 + 8) * 64 + ks * 8 + tg + 4]);
        }
    }

    float o[8][4];
    #pragma unroll
    for (int nt = 0; nt < 8; nt++)
        #pragma unroll
        for (int i = 0; i < 4; i++) o[nt][i] = 0.0f;
    float m0 = -1e30f, m1 = -1e30f, l0 = 0.0f, l1 = 0.0f;

    const int nj = 2 * qt + 2;           // K blocks of 64 covering [0, qbase+128)

    // shuffle-refragment source lanes (C-frag -> A-frag, within row quad)
    int L0 = (lane & ~3) | (tg >> 1);    // holder of col tg   (rows g, g+8)
    int L2 = L0 + 2;                     // holder of col tg+4
    bool odd = tg & 1;

    // prologue: prefetch block 0 into buffer 0
    #pragma unroll
    for (int p = 0; p < 4; p++) {
        int row = st_row + p * 16;
        cpa16(&KsBuf[0][row * KS_STRIDE + st_col], &kptr[row * 64 + st_col]);
        cpa16(&VsBuf[0][row * VS_STRIDE + st_col], &vptr[row * 64 + st_col]);
    }
    CP_COMMIT();

    for (int j = 0; j < nj; j++) {
        int s = j & 1;
        int kb = j * 64;
        CP_WAIT0();
        __syncthreads();   // buf s complete everywhere; buf s^1 reads done (prev iter)

        if (j + 1 < nj) {
            int kb2 = kb + 64;
            int d = s ^ 1;
            #pragma unroll
            for (int p = 0; p < 4; p++) {
                int row = st_row + p * 16;
                cpa16(&KsBuf[d][row * KS_STRIDE + st_col], &kptr[(kb2 + row) * 64 + st_col]);
                cpa16(&VsBuf[d][row * VS_STRIDE + st_col], &vptr[(kb2 + row) * 64 + st_col]);
            }
            CP_COMMIT();
        }

        // warp-uniform skip: all 16 rows of this warp precede the K block
        if (kb > qbase + w * 16 + 15) continue;

        const float* Kb = KsBuf[s];
        const float* Vb = VsBuf[s];

        // S = (Q/8) K^T   [16 x 64] per warp   (K already TF32-rounded: no cvt)
        float sf[8][4];
        #pragma unroll
        for (int nt = 0; nt < 8; nt++)
            #pragma unroll
            for (int i = 0; i < 4; i++) sf[nt][i] = 0.0f;

        #pragma unroll
        for (int kk = 0; kk < 8; kk++) {
            unsigned bf[8][2];
            #pragma unroll
            for (int nt = 0; nt < 8; nt++) {
                bf[nt][0] = __float_as_uint(Kb[(nt * 8 + g) * KS_STRIDE + kk * 8 + tg    ]);
                bf[nt][1] = __float_as_uint(Kb[(nt * 8 + g) * KS_STRIDE + kk * 8 + tg + 4]);
            }
            #pragma unroll
            for (int nt = 0; nt < 8; nt++) mma8(sf[nt], aq[kk], bf[nt]);
        }

        // causal mask (only blocks that can cross this warp's rows)
        if (kb + 63 > qbase + w * 16) {
            int qr0 = qbase + w * 16 + g;
            #pragma unroll
            for (int nt = 0; nt < 8; nt++) {
                int c = kb + nt * 8 + 2 * tg;
                if (c     > qr0)     sf[nt][0] = -1e30f;
                if (c + 1 > qr0)     sf[nt][1] = -1e30f;
                if (c     > qr0 + 8) sf[nt][2] = -1e30f;
                if (c + 1 > qr0 + 8) sf[nt][3] = -1e30f;
            }
        }

        // online softmax (rows g and g+8; quad reduction over tg)
        float bm0 = -1e30f, bm1 = -1e30f;
        #pragma unroll
        for (int nt = 0; nt < 8; nt++) {
            bm0 = fmaxf(bm0, fmaxf(sf[nt][0], sf[nt][1]));
            bm1 = fmaxf(bm1, fmaxf(sf[nt][2], sf[nt][3]));
        }
        bm0 = fmaxf(bm0, __shfl_xor_sync(0xffffffffu, bm0, 1));
        bm0 = fmaxf(bm0, __shfl_xor_sync(0xffffffffu, bm0, 2));
        bm1 = fmaxf(bm1, __shfl_xor_sync(0xffffffffu, bm1, 1));
        bm1 = fmaxf(bm1, __shfl_xor_sync(0xffffffffu, bm1, 2));

        float mn0 = fmaxf(m0, bm0), mn1 = fmaxf(m1, bm1);
        float al0 = __expf(m0 - mn0), al1 = __expf(m1 - mn1);
        float rs0 = 0.0f, rs1 = 0.0f;
        #pragma unroll
        for (int nt = 0; nt < 8; nt++) {
            sf[nt][0] = __expf(sf[nt][0] - mn0);
            sf[nt][1] = __expf(sf[nt][1] - mn0);
            sf[nt][2] = __expf(sf[nt][2] - mn1);
            sf[nt][3] = __expf(sf[nt][3] - mn1);
            rs0 += sf[nt][0] + sf[nt][1];
            rs1 += sf[nt][2] + sf[nt][3];
        }
        rs0 += __shfl_xor_sync(0xffffffffu, rs0, 1);
        rs0 += __shfl_xor_sync(0xffffffffu, rs0, 2);
        rs1 += __shfl_xor_sync(0xffffffffu, rs1, 1);
        rs1 += __shfl_xor_sync(0xffffffffu, rs1, 2);

        l0 = l0 * al0 + rs0;
        l1 = l1 * al1 + rs1;
        m0 = mn0; m1 = mn1;

        #pragma unroll
        for (int nt = 0; nt < 8; nt++) {
            o[nt][0] *= al0; o[nt][1] *= al0;
            o[nt][2] *= al1; o[nt][3] *= al1;
        }

        // O += P V : C-frag -> A-frag by quad shuffles (P needs cvt: fresh exp
        // outputs), V already TF32-rounded: no cvt.
        #pragma unroll
        for (int kk = 0; kk < 8; kk++) {
            float x00 = __shfl_sync(0xffffffffu, sf[kk][0], L0);
            float x01 = __shfl_sync(0xffffffffu, sf[kk][1], L0);
            float x10 = __shfl_sync(0xffffffffu, sf[kk][2], L0);
            float x11 = __shfl_sync(0xffffffffu, sf[kk][3], L0);
            float y00 = __shfl_sync(0xffffffffu, sf[kk][0], L2);
            float y01 = __shfl_sync(0xffffffffu, sf[kk][1], L2);
            float y10 = __shfl_sync(0xffffffffu, sf[kk][2], L2);
            float y11 = __shfl_sync(0xffffffffu, sf[kk][3], L2);
            unsigned ap[4];
            ap[0] = f2tf(odd ? x01 : x00);   // P[g   ][kk*8+tg  ]
            ap[1] = f2tf(odd ? x11 : x10);   // P[g+8 ][kk*8+tg  ]
            ap[2] = f2tf(odd ? y01 : y00);   // P[g   ][kk*8+tg+4]
            ap[3] = f2tf(odd ? y11 : y10);   // P[g+8 ][kk*8+tg+4]
            #pragma unroll
            for (int nt = 0; nt < 8; nt++) {
                unsigned bf2[2];
                bf2[0] = __float_as_uint(Vb[(kk * 8 + tg    ) * VS_STRIDE + nt * 8 + g]);
                bf2[1] = __float_as_uint(Vb[(kk * 8 + tg + 4) * VS_STRIDE + nt * 8 + g]);
                mma8(o[nt], ap, bf2);
            }
        }
    }

    // normalize and write to g_y [B,T,C], pre-rounded for the proj GEMM
    float il0 = 1.0f / l0, il1 = 1.0f / l1;
    int t0 = qbase + w * 16 + g;
    #pragma unroll
    for (int nt = 0; nt < 8; nt++) {
        int c = h * 64 + nt * 8 + 2 * tg;
        g_y[(b * T_ + t0    ) * C_ + c    ] = f2tff(o[nt][0] * il0);
        g_y[(b * T_ + t0    ) * C_ + c + 1] = f2tff(o[nt][1] * il0);
        g_y[(b * T_ + t0 + 8) * C_ + c    ] = f2tff(o[nt][2] * il1);
        g_y[(b * T_ + t0 + 8) * C_ + c + 1] = f2tff(o[nt][3] * il1);
    }
}

// ---------------------------------------------------------------------------
extern "C" void kernel_launch(void* const* d_in, const int* in_sizes, int n_in,
                              void* d_out, int out_size)
{
    const float* x      = (const float*)d_in[0];
    const float* W_attn = (const float*)d_in[1];
    const float* b_attn = (const float*)d_in[2];
    const float* W_proj = (const float*)d_in[3];
    const float* b_proj = (const float*)d_in[4];
    float* out = (float*)d_out;

    // opt-in to >48KB dynamic smem (idempotent; not stream-capture ops)
    cudaFuncSetAttribute(gemm_kernel,
                         cudaFuncAttributeMaxDynamicSharedMemorySize,
                         GEMM_SMEM_BYTES);
    cudaFuncSetAttribute(flash_kernel,
                         cudaFuncAttributeMaxDynamicSharedMemorySize,
                         FLASH_SMEM_BYTES);

    // device-global destinations for the pre-round pass
    float *p_x, *p_wa, *p_wp;
    cudaGetSymbolAddress((void**)&p_x,  g_x);
    cudaGetSymbolAddress((void**)&p_wa, g_wa);
    cudaGetSymbolAddress((void**)&p_wp, g_wp);

    // 0) one-time TF32 pre-rounding of GEMM operands
    round_kernel<<<(MROWS * C_ / 4 + 255) / 256, 256>>>(
        (const float4*)x, (float4*)p_x, MROWS * C_ / 4);
    round_kernel<<<(C_ * 3 * C_ / 4 + 255) / 256, 256>>>(
        (const float4*)W_attn, (float4*)p_wa, C_ * 3 * C_ / 4);
    round_kernel<<<(C_ * C_ / 4 + 255) / 256, 256>>>(
        (const float4*)W_proj, (float4*)p_wp, C_ * C_ / 4);

    // 1) QKV projection + scatter into [B,H,T,D] (TF32-rounded)
    gemm_kernel<<<dim3((3 * C_) / 128, MROWS / 128), 256, GEMM_SMEM_BYTES>>>(
        b_attn, nullptr, MROWS, 3 * C_, C_, 0);

    // 2) causal flash attention -> g_y [B,T,C] (TF32-rounded, LPT order)
    flash_kernel<<<dim3(T_ / 128, H_, B_), 256, FLASH_SMEM_BYTES>>>();

    // 3) output projection -> d_out
    gemm_kernel<<<dim3(C_ / 128, MROWS / 128), 256, GEMM_SMEM_BYTES>>>(
        b_proj, out, MROWS, C_, C_, 1);
}

// round 11
// speedup vs baseline: 1.0022x; 1.0022x over previous
#include <cuda_runtime.h>

#define B_ 2
#define T_ 2048
#define C_ 1024
#define H_ 16
#define D_ 64
#define MROWS (B_ * T_)   // 4096

// Scratch (allocation-free rule: __device__ globals). All hold TF32-grid values.
__device__ float g_q[B_ * H_ * T_ * D_];
__device__ float g_k[B_ * H_ * T_ * D_];
__device__ float g_v[B_ * H_ * T_ * D_];
__device__ float g_y[MROWS * C_];          // flash output, pre-rounded at store
__device__ float g_x[MROWS * C_];          // x, pre-rounded
__device__ float g_wa[C_ * 3 * C_];        // W_attn, pre-rounded
__device__ float g_wp[C_ * C_];            // W_proj, pre-rounded

// ---------------------------------------------------------------------------
// TF32 / async-copy helpers
// ---------------------------------------------------------------------------
__device__ __forceinline__ unsigned f2tf(float x) {
    unsigned r;
    asm("cvt.rna.tf32.f32 %0, %1;" : "=r"(r) : "f"(x));
    return r;
}
__device__ __forceinline__ float f2tff(float x) { return __uint_as_float(f2tf(x)); }

__device__ __forceinline__ void mma8(float* c, const unsigned* a, const unsigned* b) {
    asm volatile(
        "mma.sync.aligned.m16n8k8.row.col.f32.tf32.tf32.f32 "
        "{%0,%1,%2,%3},{%4,%5,%6,%7},{%8,%9},{%0,%1,%2,%3};\n"
        : "+f"(c[0]), "+f"(c[1]), "+f"(c[2]), "+f"(c[3])
        : "r"(a[0]), "r"(a[1]), "r"(a[2]), "r"(a[3]),
          "r"(b[0]), "r"(b[1]));
}

__device__ __forceinline__ void cpa16(void* smem, const void* gmem) {
    unsigned saddr = (unsigned)__cvta_generic_to_shared(smem);
    asm volatile("cp.async.cg.shared.global [%0], [%1], 16;" :: "r"(saddr), "l"(gmem));
}
#define CP_COMMIT() asm volatile("cp.async.commit_group;")
#define CP_WAIT0()  asm volatile("cp.async.wait_group 0;")

// ---------------------------------------------------------------------------
// One-time TF32 pre-rounding pass: all three operand tensors in ONE launch
// (segmented grid-stride; saves 2 launch latencies + partial-wave tails)
// ---------------------------------------------------------------------------
#define NX4  (MROWS * C_ / 4)        // 1,048,576
#define NWA4 (C_ * 3 * C_ / 4)       //   786,432
#define NWP4 (C_ * C_ / 4)           //   262,144
#define NTOT4 (NX4 + NWA4 + NWP4)    // 2,097,152

__global__ void round_all_kernel(const float4* __restrict__ sx,
                                 const float4* __restrict__ swa,
                                 const float4* __restrict__ swp,
                                 float4* __restrict__ dx,
                                 float4* __restrict__ dwa,
                                 float4* __restrict__ dwp)
{
    for (int i = blockIdx.x * blockDim.x + threadIdx.x; i < NTOT4;
         i += gridDim.x * blockDim.x) {
        const float4* s;
        float4* d;
        int idx;
        if (i < NX4)             { s = sx;  d = dx;  idx = i; }
        else if (i < NX4 + NWA4) { s = swa; d = dwa; idx = i - NX4; }
        else                     { s = swp; d = dwp; idx = i - NX4 - NWA4; }
        float4 v = s[idx];
        v.x = f2tff(v.x); v.y = f2tff(v.y);
        v.z = f2tff(v.z); v.w = f2tff(v.w);
        d[idx] = v;
    }
}

// ---------------------------------------------------------------------------
// Paired scatter for QKV epilogue: row-major [4096, 3072] -> Q/K/V [B,H,T,D]
// c0 is even, so (c0, c0+1) share head/tensor and d, d+1 are adjacent:
// one float2 (STG.64) store. Values rounded to the TF32 grid HERE.
// ---------------------------------------------------------------------------
__device__ __forceinline__ void store_qkv2(int r, int c, float v0, float v1) {
    int which = c >> 10;       // 0=q 1=k 2=v
    int cc = c & 1023;
    int h = cc >> 6;
    int d = cc & 63;
    int b = r >> 11;           // / T_
    int t = r & 2047;
    float* dst = (which == 0) ? g_q : ((which == 1) ? g_k : g_v);
    float2 p;
    p.x = f2tff(v0);
    p.y = f2tff(v1);
    *(float2*)&dst[(((b * H_ + h) * T_ + t) << 6) + d] = p;
}

// ---------------------------------------------------------------------------
// TF32 GEMM, BK=32, 2-stage cp.async pipeline: out[M,N] = A[M,K]@W[K,N]+bias
// Operands PRE-ROUNDED to the TF32 grid in gmem -> mainloop has NO cvts.
// mode 0: A = g_x,  W = g_wa, scatter-epilogue into g_q/g_k/g_v (QKV)
// mode 1: A = g_y,  W = g_wp, plain row-major epilogue into out (proj)
// BM=128, BN=128, BK=32, 256 threads (warps 4x2, warp tile 32x64)
// Dynamic smem: 2 x (A 128x36 + B 32x136) floats = 71,680 B
// ---------------------------------------------------------------------------
#define GA_STRIDE 36    // A-frag banks (4g+tg)%32 bijective; row base 144B (16-aligned)
#define GB_STRIDE 136   // B-frag banks (8tg+g)%32 bijective; row base 544B (16-aligned)
#define GA_FLOATS (128 * GA_STRIDE)   // per stage: 4608
#define GB_FLOATS (32 * GB_STRIDE)    // per stage: 4352
#define GEMM_SMEM_BYTES ((2 * (GA_FLOATS + GB_FLOATS)) * 4)   // 71680

__global__ __launch_bounds__(256, 2)
void gemm_kernel(const float* __restrict__ bias, float* __restrict__ out,
                 int M, int N, int K, int mode)
{
    extern __shared__ __align__(16) float gsm[];
    float* Asm = gsm;                       // [2][128][GA_STRIDE]
    float* Bsm = gsm + 2 * GA_FLOATS;       // [2][32][GB_STRIDE]
#define AS(s, r, c) Asm[((s) * 128 + (r)) * GA_STRIDE + (c)]
#define BS(s, k, n) Bsm[((s) * 32 + (k)) * GB_STRIDE + (n)]

    const float* Ap = (mode == 1) ? g_y : g_x;
    const float* W  = (mode == 1) ? g_wp : g_wa;

    int tid = threadIdx.x;
    int warp = tid >> 5, lane = tid & 31;
    int g = lane >> 2, tg = lane & 3;
    int wm = warp >> 1, wn = warp & 1;
    int bm = blockIdx.y * 128, bn = blockIdx.x * 128;

    // staging coords: A 128x32 = 1024 float4 (4/thread), B 32x128 = 1024 float4
    int a_row = tid >> 3,  a_col = (tid & 7) * 4;    // rows 0..31 (+32/pass)
    int b_kr  = tid >> 5,  b_nq  = (tid & 31) * 4;   // k-rows 0..7 (+8/pass)

    float acc[2][8][4];
    #pragma unroll
    for (int mt = 0; mt < 2; mt++)
        #pragma unroll
        for (int nt = 0; nt < 8; nt++)
            #pragma unroll
            for (int i = 0; i < 4; i++) acc[mt][nt][i] = 0.0f;

    const int nst = K >> 5;   // K/32 stages (=32 here)

    // prologue: prefetch stage 0 into buffer 0
    #pragma unroll
    for (int p = 0; p < 4; p++) {
        int ar = a_row + p * 32;
        cpa16(&AS(0, ar, a_col), &Ap[(bm + ar) * K + a_col]);
        int kr = b_kr + p * 8;
        cpa16(&BS(0, kr, b_nq),  &W[kr * N + bn + b_nq]);
    }
    CP_COMMIT();

    for (int it = 0; it < nst; it++) {
        int s = it & 1;
        CP_WAIT0();
        __syncthreads();   // stage `it` resident; buf s^1 readers (iter it-1) done

        if (it + 1 < nst) {
            int k0 = (it + 1) << 5;
            int d = s ^ 1;
            #pragma unroll
            for (int p = 0; p < 4; p++) {
                int ar = a_row + p * 32;
                cpa16(&AS(d, ar, a_col), &Ap[(bm + ar) * K + k0 + a_col]);
                int kr = b_kr + p * 8;
                cpa16(&BS(d, kr, b_nq),  &W[(k0 + kr) * N + bn + b_nq]);
            }
            CP_COMMIT();
        }

        #pragma unroll
        for (int kk = 0; kk < 4; kk++) {
            unsigned af[2][4], bf[8][2];
            #pragma unroll
            for (int mt = 0; mt < 2; mt++) {
                int r = wm * 32 + mt * 16 + g;
                af[mt][0] = __float_as_uint(AS(s, r,     kk * 8 + tg    ));
                af[mt][1] = __float_as_uint(AS(s, r + 8, kk * 8 + tg    ));
                af[mt][2] = __float_as_uint(AS(s, r,     kk * 8 + tg + 4));
                af[mt][3] = __float_as_uint(AS(s, r + 8, kk * 8 + tg + 4));
            }
            #pragma unroll
            for (int nt = 0; nt < 8; nt++) {
                int c = wn * 64 + nt * 8 + g;
                bf[nt][0] = __float_as_uint(BS(s, kk * 8 + tg,     c));
                bf[nt][1] = __float_as_uint(BS(s, kk * 8 + tg + 4, c));
            }
            #pragma unroll
            for (int mt = 0; mt < 2; mt++)
                #pragma unroll
                for (int nt = 0; nt < 8; nt++)
                    mma8(acc[mt][nt], af[mt], bf[nt]);
        }
        // next iteration's top __syncthreads (after CP_WAIT0) protects buf reuse
    }

    // epilogue (paired float2 loads/stores; c0 even -> 8B-aligned)
    #pragma unroll
    for (int mt = 0; mt < 2; mt++) {
        int r0 = bm + wm * 32 + mt * 16 + g;
        #pragma unroll
        for (int nt = 0; nt < 8; nt++) {
            int c0 = bn + wn * 64 + nt * 8 + 2 * tg;
            float2 bb = *(const float2*)&bias[c0];
            #pragma unroll
            for (int half = 0; half < 2; half++) {
                int r = r0 + half * 8;
                float v0 = acc[mt][nt][half * 2 + 0] + bb.x;
                float v1 = acc[mt][nt][half * 2 + 1] + bb.y;
                if (mode == 0) {
                    store_qkv2(r, c0, v0, v1);
                } else {
                    float2 p; p.x = v0; p.y = v1;
                    *(float2*)&out[r * N + c0] = p;
                }
            }
        }
    }
#undef AS
#undef BS
}

// ---------------------------------------------------------------------------
// Flash attention v2: CTA per (qtile=128 rows, h, b). 8 warps, 16 q-rows each.
// Double-buffered cp.async K/V staging (dynamic smem, 71,680 B).
// K/V/Q are pre-rounded to TF32 in gmem -> smem loads feed mma with NO cvt.
// P refragmented C->A via intra-quad shuffles (no smem bounce, 1 sync/iter).
// Output g_y stored pre-rounded (proj GEMM consumes it cvt-free).
// LPT scheduling: heaviest q-tiles get the LOWEST blockIdx.x (wave 1 start).
// __launch_bounds__(256,2): cap at 128 regs -> 2 CTAs/SM (smem 143KB < 228KB)
// -> 4 warps/SMSP for latency hiding (was 2).
// ---------------------------------------------------------------------------
#define KS_STRIDE 68   // S B-frag bank = 4g+tg (mod 32): bijective, conflict-free
#define VS_STRIDE 72   // PV B-frag bank = 8tg+g (mod 32): bijective, conflict-free
#define KS_FLOATS (64 * KS_STRIDE)            // 4352
#define VS_FLOATS (64 * VS_STRIDE)            // 4608
#define FLASH_SMEM_BYTES ((2 * (KS_FLOATS + VS_FLOATS)) * 4)   // 71680

__global__ __launch_bounds__(256, 2)
void flash_kernel()
{
    extern __shared__ __align__(16) float smem[];
    // layout: Ks[0], Ks[1], Vs[0], Vs[1]
    float* KsBuf[2] = { smem,                smem + KS_FLOATS };
    float* VsBuf[2] = { smem + 2*KS_FLOATS,  smem + 2*KS_FLOATS + VS_FLOATS };

    int b = blockIdx.z, h = blockIdx.y;
    int qt = gridDim.x - 1 - blockIdx.x;   // longest-processing-time-first
    int tid = threadIdx.x, w = tid >> 5, lane = tid & 31;
    int g = lane >> 2, tg = lane & 3;
    int qbase = qt * 128;

    const float* qptr = g_q + (((b * H_ + h) * T_) << 6);
    const float* kptr = g_k + (((b * H_ + h) * T_) << 6);
    const float* vptr = g_v + (((b * H_ + h) * T_) << 6);

    // per-thread staging coords: 4 float4 per tile (256 thr x 4 x 16B = 16KB)
    int st_row = tid >> 4;            // 0..15 (+16 per pass)
    int st_col = (tid & 15) * 4;

    // Q fragments, pre-scaled by 1/sqrt(D)=0.125 (exact exponent shift:
    // commutes with TF32 rounding; q values already on the TF32 grid)
    unsigned aq[8][4];
    {
        int r0 = qbase + w * 16 + g;
        #pragma unroll
        for (int ks = 0; ks < 8; ks++) {
            aq[ks][0] = __float_as_uint(0.125f * qptr[ r0      * 64 + ks * 8 + tg    ]);
            aq[ks][1] = __float_as_uint(0.125f * qptr[(r0 + 8) * 64 + ks * 8 + tg    ]);
            aq[ks][2] = __float_as_uint(0.125f * qptr[ r0      * 64 + ks * 8 + tg + 4]);
            aq[ks][3] = __float_as_uint(0.125f * qptr[(r0 + 8) * 64 + ks * 8 + tg + 4]);
        }
    }

    float o[8][4];
    #pragma unroll
    for (int nt = 0; nt < 8; nt++)
        #pragma unroll
        for (int i = 0; i < 4; i++) o[nt][i] = 0.0f;
    float m0 = -1e30f, m1 = -1e30f, l0 = 0.0f, l1 = 0.0f;

    const int nj = 2 * qt + 2;           // K blocks of 64 covering [0, qbase+128)

    // shuffle-refragment source lanes (C-frag -> A-frag, within row quad)
    int L0 = (lane & ~3) | (tg >> 1);    // holder of col tg   (rows g, g+8)
    int L2 = L0 + 2;                     // holder of col tg+4
    bool odd = tg & 1;

    // prologue: prefetch block 0 into buffer 0
    #pragma unroll
    for (int p = 0; p < 4; p++) {
        int row = st_row + p * 16;
        cpa16(&KsBuf[0][row * KS_STRIDE + st_col], &kptr[row * 64 + st_col]);
        cpa16(&VsBuf[0][row * VS_STRIDE + st_col], &vptr[row * 64 + st_col]);
    }
    CP_COMMIT();

    for (int j = 0; j < nj; j++) {
        int s = j & 1;
        int kb = j * 64;
        CP_WAIT0();
        __syncthreads();   // buf s complete everywhere; buf s^1 reads done (prev iter)

        if (j + 1 < nj) {
            int kb2 = kb + 64;
            int d = s ^ 1;
            #pragma unroll
            for (int p = 0; p < 4; p++) {
                int row = st_row + p * 16;
                cpa16(&KsBuf[d][row * KS_STRIDE + st_col], &kptr[(kb2 + row) * 64 + st_col]);
                cpa16(&VsBuf[d][row * VS_STRIDE + st_col], &vptr[(kb2 + row) * 64 + st_col]);
            }
            CP_COMMIT();
        }

        // warp-uniform skip: all 16 rows of this warp precede the K block
        if (kb > qbase + w * 16 + 15) continue;

        const float* Kb = KsBuf[s];
        const float* Vb = VsBuf[s];

        // S = (Q/8) K^T   [16 x 64] per warp   (K already TF32-rounded: no cvt)
        float sf[8][4];
        #pragma unroll
        for (int nt = 0; nt < 8; nt++)
            #pragma unroll
            for (int i = 0; i < 4; i++) sf[nt][i] = 0.0f;

        #pragma unroll
        for (int kk = 0; kk < 8; kk++) {
            unsigned bf[8][2];
            #pragma unroll
            for (int nt = 0; nt < 8; nt++) {
                bf[nt][0] = __float_as_uint(Kb[(nt * 8 + g) * KS_STRIDE + kk * 8 + tg    ]);
                bf[nt][1] = __float_as_uint(Kb[(nt * 8 + g) * KS_STRIDE + kk * 8 + tg + 4]);
            }
            #pragma unroll
            for (int nt = 0; nt < 8; nt++) mma8(sf[nt], aq[kk], bf[nt]);
        }

        // causal mask (only blocks that can cross this warp's rows)
        if (kb + 63 > qbase + w * 16) {
            int qr0 = qbase + w * 16 + g;
            #pragma unroll
            for (int nt = 0; nt < 8; nt++) {
                int c = kb + nt * 8 + 2 * tg;
                if (c     > qr0)     sf[nt][0] = -1e30f;
                if (c + 1 > qr0)     sf[nt][1] = -1e30f;
                if (c     > qr0 + 8) sf[nt][2] = -1e30f;
                if (c + 1 > qr0 + 8) sf[nt][3] = -1e30f;
            }
        }

        // online softmax (rows g and g+8; quad reduction over tg)
        float bm0 = -1e30f, bm1 = -1e30f;
        #pragma unroll
        for (int nt = 0; nt < 8; nt++) {
            bm0 = fmaxf(bm0, fmaxf(sf[nt][0], sf[nt][1]));
            bm1 = fmaxf(bm1, fmaxf(sf[nt][2], sf[nt][3]));
        }
        bm0 = fmaxf(bm0, __shfl_xor_sync(0xffffffffu, bm0, 1));
        bm0 = fmaxf(bm0, __shfl_xor_sync(0xffffffffu, bm0, 2));
        bm1 = fmaxf(bm1, __shfl_xor_sync(0xffffffffu, bm1, 1));
        bm1 = fmaxf(bm1, __shfl_xor_sync(0xffffffffu, bm1, 2));

        float mn0 = fmaxf(m0, bm0), mn1 = fmaxf(m1, bm1);
        float al0 = __expf(m0 - mn0), al1 = __expf(m1 - mn1);
        float rs0 = 0.0f, rs1 = 0.0f;
        #pragma unroll
        for (int nt = 0; nt < 8; nt++) {
            sf[nt][0] = __expf(sf[nt][0] - mn0);
            sf[nt][1] = __expf(sf[nt][1] - mn0);
            sf[nt][2] = __expf(sf[nt][2] - mn1);
            sf[nt][3] = __expf(sf[nt][3] - mn1);
            rs0 += sf[nt][0] + sf[nt][1];
            rs1 += sf[nt][2] + sf[nt][3];
        }
        rs0 += __shfl_xor_sync(0xffffffffu, rs0, 1);
        rs0 += __shfl_xor_sync(0xffffffffu, rs0, 2);
        rs1 += __shfl_xor_sync(0xffffffffu, rs1, 1);
        rs1 += __shfl_xor_sync(0xffffffffu, rs1, 2);

        l0 = l0 * al0 + rs0;
        l1 = l1 * al1 + rs1;
        m0 = mn0; m1 = mn1;

        #pragma unroll
        for (int nt = 0; nt < 8; nt++) {
            o[nt][0] *= al0; o[nt][1] *= al0;
            o[nt][2] *= al1; o[nt][3] *= al1;
        }

        // O += P V : C-frag -> A-frag by quad shuffles (P needs cvt: fresh exp
        // outputs), V already TF32-rounded: no cvt.
        #pragma unroll
        for (int kk = 0; kk < 8; kk++) {
            float x00 = __shfl_sync(0xffffffffu, sf[kk][0], L0);
            float x01 = __shfl_sync(0xffffffffu, sf[kk][1], L0);
            float x10 = __shfl_sync(0xffffffffu, sf[kk][2], L0);
            float x11 = __shfl_sync(0xffffffffu, sf[kk][3], L0);
            float y00 = __shfl_sync(0xffffffffu, sf[kk][0], L2);
            float y01 = __shfl_sync(0xffffffffu, sf[kk][1], L2);
            float y10 = __shfl_sync(0xffffffffu, sf[kk][2], L2);
            float y11 = __shfl_sync(0xffffffffu, sf[kk][3], L2);
            unsigned ap[4];
            ap[0] = f2tf(odd ? x01 : x00);   // P[g   ][kk*8+tg  ]
            ap[1] = f2tf(odd ? x11 : x10);   // P[g+8 ][kk*8+tg  ]
            ap[2] = f2tf(odd ? y01 : y00);   // P[g   ][kk*8+tg+4]
            ap[3] = f2tf(odd ? y11 : y10);   // P[g+8 ][kk*8+tg+4]
            #pragma unroll
            for (int nt = 0; nt < 8; nt++) {
                unsigned bf2[2];
                bf2[0] = __float_as_uint(Vb[(kk * 8 + tg    ) * VS_STRIDE + nt * 8 + g]);
                bf2[1] = __float_as_uint(Vb[(kk * 8 + tg + 4) * VS_STRIDE + nt * 8 + g]);
                mma8(o[nt], ap, bf2);
            }
        }
    }

    // normalize and write to g_y [B,T,C], pre-rounded for the proj GEMM
    float il0 = 1.0f / l0, il1 = 1.0f / l1;
    int t0 = qbase + w * 16 + g;
    #pragma unroll
    for (int nt = 0; nt < 8; nt++) {
        int c = h * 64 + nt * 8 + 2 * tg;
        g_y[(b * T_ + t0    ) * C_ + c    ] = f2tff(o[nt][0] * il0);
        g_y[(b * T_ + t0    ) * C_ + c + 1] = f2tff(o[nt][1] * il0);
        g_y[(b * T_ + t0 + 8) * C_ + c    ] = f2tff(o[nt][2] * il1);
        g_y[(b * T_ + t0 + 8) * C_ + c + 1] = f2tff(o[nt][3] * il1);
    }
}

// ---------------------------------------------------------------------------
extern "C" void kernel_launch(void* const* d_in, const int* in_sizes, int n_in,
                              void* d_out, int out_size)
{
    const float* x      = (const float*)d_in[0];
    const float* W_attn = (const float*)d_in[1];
    const float* b_attn = (const float*)d_in[2];
    const float* W_proj = (const float*)d_in[3];
    const float* b_proj = (const float*)d_in[4];
    float* out = (float*)d_out;

    // opt-in to >48KB dynamic smem (idempotent; not stream-capture ops)
    cudaFuncSetAttribute(gemm_kernel,
                         cudaFuncAttributeMaxDynamicSharedMemorySize,
                         GEMM_SMEM_BYTES);
    cudaFuncSetAttribute(flash_kernel,
                         cudaFuncAttributeMaxDynamicSharedMemorySize,
                         FLASH_SMEM_BYTES);

    // device-global destinations for the pre-round pass
    float *p_x, *p_wa, *p_wp;
    cudaGetSymbolAddress((void**)&p_x,  g_x);
    cudaGetSymbolAddress((void**)&p_wa, g_wa);
    cudaGetSymbolAddress((void**)&p_wp, g_wp);

    // 0) one-time TF32 pre-rounding of all GEMM operands (single launch)
    round_all_kernel<<<2048, 256>>>(
        (const float4*)x, (const float4*)W_attn, (const float4*)W_proj,
        (float4*)p_x, (float4*)p_wa, (float4*)p_wp);

    // 1) QKV projection + scatter into [B,H,T,D] (TF32-rounded)
    gemm_kernel<<<dim3((3 * C_) / 128, MROWS / 128), 256, GEMM_SMEM_BYTES>>>(
        b_attn, nullptr, MROWS, 3 * C_, C_, 0);

    // 2) causal flash attention -> g_y [B,T,C] (TF32-rounded, LPT order)
    flash_kernel<<<dim3(T_ / 128, H_, B_), 256, FLASH_SMEM_BYTES>>>();

    // 3) output projection -> d_out
    gemm_kernel<<<dim3(C_ / 128, MROWS / 128), 256, GEMM_SMEM_BYTES>>>(
        b_proj, out, MROWS, C_, C_, 1);
}

// round 14
// speedup vs baseline: 1.0358x; 1.0335x over previous
#include <cuda_runtime.h>

#define B_ 2
#define T_ 2048
#define C_ 1024
#define H_ 16
#define D_ 64
#define MROWS (B_ * T_)   // 4096

// Scratch (allocation-free rule: __device__ globals). All hold TF32-grid values.
__device__ float g_q[B_ * H_ * T_ * D_];
__device__ float g_k[B_ * H_ * T_ * D_];
__device__ float g_v[B_ * H_ * T_ * D_];
__device__ float g_y[MROWS * C_];          // flash output, pre-rounded at store
__device__ float g_x[MROWS * C_];          // x, pre-rounded
__device__ float g_wa[C_ * 3 * C_];        // W_attn, pre-rounded
__device__ float g_wp[C_ * C_];            // W_proj, pre-rounded

// ---------------------------------------------------------------------------
// TF32 / async-copy helpers
// ---------------------------------------------------------------------------
__device__ __forceinline__ unsigned f2tf(float x) {
    unsigned r;
    asm("cvt.rna.tf32.f32 %0, %1;" : "=r"(r) : "f"(x));
    return r;
}
__device__ __forceinline__ float f2tff(float x) { return __uint_as_float(f2tf(x)); }

__device__ __forceinline__ void mma8(float* c, const unsigned* a, const unsigned* b) {
    asm volatile(
        "mma.sync.aligned.m16n8k8.row.col.f32.tf32.tf32.f32 "
        "{%0,%1,%2,%3},{%4,%5,%6,%7},{%8,%9},{%0,%1,%2,%3};\n"
        : "+f"(c[0]), "+f"(c[1]), "+f"(c[2]), "+f"(c[3])
        : "r"(a[0]), "r"(a[1]), "r"(a[2]), "r"(a[3]),
          "r"(b[0]), "r"(b[1]));
}

__device__ __forceinline__ void cpa16(void* smem, const void* gmem) {
    unsigned saddr = (unsigned)__cvta_generic_to_shared(smem);
    asm volatile("cp.async.cg.shared.global [%0], [%1], 16;" :: "r"(saddr), "l"(gmem));
}
#define CP_COMMIT() asm volatile("cp.async.commit_group;")
#define CP_WAIT0()  asm volatile("cp.async.wait_group 0;")

// ---------------------------------------------------------------------------
// One-time TF32 pre-rounding pass: all three operand tensors in ONE launch
// ---------------------------------------------------------------------------
#define NX4  (MROWS * C_ / 4)        // 1,048,576
#define NWA4 (C_ * 3 * C_ / 4)       //   786,432
#define NWP4 (C_ * C_ / 4)           //   262,144
#define NTOT4 (NX4 + NWA4 + NWP4)    // 2,097,152

__global__ void round_all_kernel(const float4* __restrict__ sx,
                                 const float4* __restrict__ swa,
                                 const float4* __restrict__ swp,
                                 float4* __restrict__ dx,
                                 float4* __restrict__ dwa,
                                 float4* __restrict__ dwp)
{
    for (int i = blockIdx.x * blockDim.x + threadIdx.x; i < NTOT4;
         i += gridDim.x * blockDim.x) {
        const float4* s;
        float4* d;
        int idx;
        if (i < NX4)             { s = sx;  d = dx;  idx = i; }
        else if (i < NX4 + NWA4) { s = swa; d = dwa; idx = i - NX4; }
        else                     { s = swp; d = dwp; idx = i - NX4 - NWA4; }
        float4 v = s[idx];
        v.x = f2tff(v.x); v.y = f2tff(v.y);
        v.z = f2tff(v.z); v.w = f2tff(v.w);
        d[idx] = v;
    }
}

// ---------------------------------------------------------------------------
// Paired scatter for QKV epilogue -> Q/K/V [B,H,T,D] (TF32-rounded here)
// ---------------------------------------------------------------------------
__device__ __forceinline__ void store_qkv2(int r, int c, float v0, float v1) {
    int which = c >> 10;       // 0=q 1=k 2=v
    int cc = c & 1023;
    int h = cc >> 6;
    int d = cc & 63;
    int b = r >> 11;           // / T_
    int t = r & 2047;
    float* dst = (which == 0) ? g_q : ((which == 1) ? g_k : g_v);
    float2 p;
    p.x = f2tff(v0);
    p.y = f2tff(v1);
    *(float2*)&dst[(((b * H_ + h) * T_ + t) << 6) + d] = p;
}

// ---------------------------------------------------------------------------
// TF32 GEMM, BK=32, 2-stage cp.async pipeline (UNCHANGED from 460us baseline)
// ---------------------------------------------------------------------------
#define GA_STRIDE 36
#define GB_STRIDE 136
#define GA_FLOATS (128 * GA_STRIDE)
#define GB_FLOATS (32 * GB_STRIDE)
#define GEMM_SMEM_BYTES ((2 * (GA_FLOATS + GB_FLOATS)) * 4)   // 71680

__global__ __launch_bounds__(256, 2)
void gemm_kernel(const float* __restrict__ bias, float* __restrict__ out,
                 int M, int N, int K, int mode)
{
    extern __shared__ __align__(16) float gsm[];
    float* Asm = gsm;
    float* Bsm = gsm + 2 * GA_FLOATS;
#define AS(s, r, c) Asm[((s) * 128 + (r)) * GA_STRIDE + (c)]
#define BS(s, k, n) Bsm[((s) * 32 + (k)) * GB_STRIDE + (n)]

    const float* Ap = (mode == 1) ? g_y : g_x;
    const float* W  = (mode == 1) ? g_wp : g_wa;

    int tid = threadIdx.x;
    int warp = tid >> 5, lane = tid & 31;
    int g = lane >> 2, tg = lane & 3;
    int wm = warp >> 1, wn = warp & 1;
    int bm = blockIdx.y * 128, bn = blockIdx.x * 128;

    int a_row = tid >> 3,  a_col = (tid & 7) * 4;
    int b_kr  = tid >> 5,  b_nq  = (tid & 31) * 4;

    float acc[2][8][4];
    #pragma unroll
    for (int mt = 0; mt < 2; mt++)
        #pragma unroll
        for (int nt = 0; nt < 8; nt++)
            #pragma unroll
            for (int i = 0; i < 4; i++) acc[mt][nt][i] = 0.0f;

    const int nst = K >> 5;

    #pragma unroll
    for (int p = 0; p < 4; p++) {
        int ar = a_row + p * 32;
        cpa16(&AS(0, ar, a_col), &Ap[(bm + ar) * K + a_col]);
        int kr = b_kr + p * 8;
        cpa16(&BS(0, kr, b_nq),  &W[kr * N + bn + b_nq]);
    }
    CP_COMMIT();

    for (int it = 0; it < nst; it++) {
        int s = it & 1;
        CP_WAIT0();
        __syncthreads();

        if (it + 1 < nst) {
            int k0 = (it + 1) << 5;
            int d = s ^ 1;
            #pragma unroll
            for (int p = 0; p < 4; p++) {
                int ar = a_row + p * 32;
                cpa16(&AS(d, ar, a_col), &Ap[(bm + ar) * K + k0 + a_col]);
                int kr = b_kr + p * 8;
                cpa16(&BS(d, kr, b_nq),  &W[(k0 + kr) * N + bn + b_nq]);
            }
            CP_COMMIT();
        }

        #pragma unroll
        for (int kk = 0; kk < 4; kk++) {
            unsigned af[2][4], bf[8][2];
            #pragma unroll
            for (int mt = 0; mt < 2; mt++) {
                int r = wm * 32 + mt * 16 + g;
                af[mt][0] = __float_as_uint(AS(s, r,     kk * 8 + tg    ));
                af[mt][1] = __float_as_uint(AS(s, r + 8, kk * 8 + tg    ));
                af[mt][2] = __float_as_uint(AS(s, r,     kk * 8 + tg + 4));
                af[mt][3] = __float_as_uint(AS(s, r + 8, kk * 8 + tg + 4));
            }
            #pragma unroll
            for (int nt = 0; nt < 8; nt++) {
                int c = wn * 64 + nt * 8 + g;
                bf[nt][0] = __float_as_uint(BS(s, kk * 8 + tg,     c));
                bf[nt][1] = __float_as_uint(BS(s, kk * 8 + tg + 4, c));
            }
            #pragma unroll
            for (int mt = 0; mt < 2; mt++)
                #pragma unroll
                for (int nt = 0; nt < 8; nt++)
                    mma8(acc[mt][nt], af[mt], bf[nt]);
        }
    }

    // epilogue (paired float2 loads/stores; c0 even)
    #pragma unroll
    for (int mt = 0; mt < 2; mt++) {
        int r0 = bm + wm * 32 + mt * 16 + g;
        #pragma unroll
        for (int nt = 0; nt < 8; nt++) {
            int c0 = bn + wn * 64 + nt * 8 + 2 * tg;
            float2 bb = *(const float2*)&bias[c0];
            #pragma unroll
            for (int half = 0; half < 2; half++) {
                int r = r0 + half * 8;
                float v0 = acc[mt][nt][half * 2 + 0] + bb.x;
                float v1 = acc[mt][nt][half * 2 + 1] + bb.y;
                if (mode == 0) {
                    store_qkv2(r, c0, v0, v1);
                } else {
                    float2 p; p.x = v0; p.y = v1;
                    *(float2*)&out[r * N + c0] = p;
                }
            }
        }
    }
#undef AS
#undef BS
}

// ---------------------------------------------------------------------------
// Flash attention v3: CTA per (qtile=256 rows, h, b). 8 warps, 32 q-rows each
// (warp tile 32x64, mt in {0,1}). B-fragments (K/V smem reads) are SHARED
// across the two mt row-tiles -> smem bytes per MAC halved vs v2.
// Double-buffered cp.async K/V staging; exp2f softmax (log2e folded into Q
// scale); LPT block order. __launch_bounds__(256,1): ~230 regs, 1 CTA/SM.
// ---------------------------------------------------------------------------
#define KS_STRIDE 68
#define VS_STRIDE 72
#define KS_FLOATS (64 * KS_STRIDE)            // 4352
#define VS_FLOATS (64 * VS_STRIDE)            // 4608
#define FLASH_SMEM_BYTES ((2 * (KS_FLOATS + VS_FLOATS)) * 4)   // 71680

__global__ __launch_bounds__(256, 1)
void flash_kernel()
{
    extern __shared__ __align__(16) float smem[];
    float* KsBuf[2] = { smem,                smem + KS_FLOATS };
    float* VsBuf[2] = { smem + 2*KS_FLOATS,  smem + 2*KS_FLOATS + VS_FLOATS };

    int b = blockIdx.z, h = blockIdx.y;
    int qt = gridDim.x - 1 - blockIdx.x;   // LPT: heaviest tiles first
    int tid = threadIdx.x, w = tid >> 5, lane = tid & 31;
    int g = lane >> 2, tg = lane & 3;
    int qbase = qt * 256;

    const float* qptr = g_q + (((b * H_ + h) * T_) << 6);
    const float* kptr = g_k + (((b * H_ + h) * T_) << 6);
    const float* vptr = g_v + (((b * H_ + h) * T_) << 6);

    // staging: 4 float4 per tile per thread (256 thr)
    int st_row = tid >> 4;
    int st_col = (tid & 15) * 4;

    // Q fragments, scaled by (1/8)*log2(e): softmax uses exp2 directly.
    const float QS = 0.125f * 1.44269504088896340736f;
    unsigned aq[2][8][4];
    #pragma unroll
    for (int mt = 0; mt < 2; mt++) {
        int r0 = qbase + w * 32 + mt * 16 + g;
        #pragma unroll
        for (int ks = 0; ks < 8; ks++) {
            aq[mt][ks][0] = __float_as_uint(QS * qptr[ r0      * 64 + ks * 8 + tg    ]);
            aq[mt][ks][1] = __float_as_uint(QS * qptr[(r0 + 8) * 64 + ks * 8 + tg    ]);
            aq[mt][ks][2] = __float_as_uint(QS * qptr[ r0      * 64 + ks * 8 + tg + 4]);
            aq[mt][ks][3] = __float_as_uint(QS * qptr[(r0 + 8) * 64 + ks * 8 + tg + 4]);
        }
    }

    float o[2][8][4];
    float m_[2][2], l_[2][2];
    #pragma unroll
    for (int mt = 0; mt < 2; mt++) {
        #pragma unroll
        for (int nt = 0; nt < 8; nt++)
            #pragma unroll
            for (int i = 0; i < 4; i++) o[mt][nt][i] = 0.0f;
        m_[mt][0] = -1e30f; m_[mt][1] = -1e30f;
        l_[mt][0] = 0.0f;   l_[mt][1] = 0.0f;
    }

    const int nj = 4 * qt + 4;           // 64-blocks covering [0, qbase+256)

    int L0 = (lane & ~3) | (tg >> 1);
    int L2 = L0 + 2;
    bool odd = tg & 1;

    #pragma unroll
    for (int p = 0; p < 4; p++) {
        int row = st_row + p * 16;
        cpa16(&KsBuf[0][row * KS_STRIDE + st_col], &kptr[row * 64 + st_col]);
        cpa16(&VsBuf[0][row * VS_STRIDE + st_col], &vptr[row * 64 + st_col]);
    }
    CP_COMMIT();

    for (int j = 0; j < nj; j++) {
        int s = j & 1;
        int kb = j * 64;
        CP_WAIT0();
        __syncthreads();

        if (j + 1 < nj) {
            int kb2 = kb + 64;
            int d = s ^ 1;
            #pragma unroll
            for (int p = 0; p < 4; p++) {
                int row = st_row + p * 16;
                cpa16(&KsBuf[d][row * KS_STRIDE + st_col], &kptr[(kb2 + row) * 64 + st_col]);
                cpa16(&VsBuf[d][row * VS_STRIDE + st_col], &vptr[(kb2 + row) * 64 + st_col]);
            }
            CP_COMMIT();
        }

        // warp-uniform skip: all 32 rows of this warp precede the K block
        if (kb > qbase + w * 32 + 31) continue;

        const float* Kb = KsBuf[s];
        const float* Vb = VsBuf[s];

        // S = (Q*QS) K^T : [32 x 64] per warp, B-frags shared across mt
        float sf[2][8][4];
        #pragma unroll
        for (int mt = 0; mt < 2; mt++)
            #pragma unroll
            for (int nt = 0; nt < 8; nt++)
                #pragma unroll
                for (int i = 0; i < 4; i++) sf[mt][nt][i] = 0.0f;

        #pragma unroll
        for (int kk = 0; kk < 8; kk++) {
            unsigned bf[8][2];
            #pragma unroll
            for (int nt = 0; nt < 8; nt++) {
                bf[nt][0] = __float_as_uint(Kb[(nt * 8 + g) * KS_STRIDE + kk * 8 + tg    ]);
                bf[nt][1] = __float_as_uint(Kb[(nt * 8 + g) * KS_STRIDE + kk * 8 + tg + 4]);
            }
            #pragma unroll
            for (int mt = 0; mt < 2; mt++)
                #pragma unroll
                for (int nt = 0; nt < 8; nt++)
                    mma8(sf[mt][nt], aq[mt][kk], bf[nt]);
        }

        // causal mask per mt
        #pragma unroll
        for (int mt = 0; mt < 2; mt++) {
            if (kb + 63 > qbase + w * 32 + mt * 16) {
                int qr0 = qbase + w * 32 + mt * 16 + g;
                #pragma unroll
                for (int nt = 0; nt < 8; nt++) {
                    int c = kb + nt * 8 + 2 * tg;
                    if (c     > qr0)     sf[mt][nt][0] = -1e30f;
                    if (c + 1 > qr0)     sf[mt][nt][1] = -1e30f;
                    if (c     > qr0 + 8) sf[mt][nt][2] = -1e30f;
                    if (c + 1 > qr0 + 8) sf[mt][nt][3] = -1e30f;
                }
            }
        }

        // online softmax per mt (base-2; Q pre-scaled by log2e)
        #pragma unroll
        for (int mt = 0; mt < 2; mt++) {
            float bm0 = -1e30f, bm1 = -1e30f;
            #pragma unroll
            for (int nt = 0; nt < 8; nt++) {
                bm0 = fmaxf(bm0, fmaxf(sf[mt][nt][0], sf[mt][nt][1]));
                bm1 = fmaxf(bm1, fmaxf(sf[mt][nt][2], sf[mt][nt][3]));
            }
            bm0 = fmaxf(bm0, __shfl_xor_sync(0xffffffffu, bm0, 1));
            bm0 = fmaxf(bm0, __shfl_xor_sync(0xffffffffu, bm0, 2));
            bm1 = fmaxf(bm1, __shfl_xor_sync(0xffffffffu, bm1, 1));
            bm1 = fmaxf(bm1, __shfl_xor_sync(0xffffffffu, bm1, 2));

            float mn0 = fmaxf(m_[mt][0], bm0), mn1 = fmaxf(m_[mt][1], bm1);
            float al0 = exp2f(m_[mt][0] - mn0), al1 = exp2f(m_[mt][1] - mn1);
            float rs0 = 0.0f, rs1 = 0.0f;
            #pragma unroll
            for (int nt = 0; nt < 8; nt++) {
                sf[mt][nt][0] = exp2f(sf[mt][nt][0] - mn0);
                sf[mt][nt][1] = exp2f(sf[mt][nt][1] - mn0);
                sf[mt][nt][2] = exp2f(sf[mt][nt][2] - mn1);
                sf[mt][nt][3] = exp2f(sf[mt][nt][3] - mn1);
                rs0 += sf[mt][nt][0] + sf[mt][nt][1];
                rs1 += sf[mt][nt][2] + sf[mt][nt][3];
            }
            rs0 += __shfl_xor_sync(0xffffffffu, rs0, 1);
            rs0 += __shfl_xor_sync(0xffffffffu, rs0, 2);
            rs1 += __shfl_xor_sync(0xffffffffu, rs1, 1);
            rs1 += __shfl_xor_sync(0xffffffffu, rs1, 2);

            l_[mt][0] = l_[mt][0] * al0 + rs0;
            l_[mt][1] = l_[mt][1] * al1 + rs1;
            m_[mt][0] = mn0; m_[mt][1] = mn1;

            #pragma unroll
            for (int nt = 0; nt < 8; nt++) {
                o[mt][nt][0] *= al0; o[mt][nt][1] *= al0;
                o[mt][nt][2] *= al1; o[mt][nt][3] *= al1;
            }
        }

        // O += P V : P refrag per mt via quad shuffles; V B-frags shared
        #pragma unroll
        for (int kk = 0; kk < 8; kk++) {
            unsigned ap[2][4];
            #pragma unroll
            for (int mt = 0; mt < 2; mt++) {
                float x00 = __shfl_sync(0xffffffffu, sf[mt][kk][0], L0);
                float x01 = __shfl_sync(0xffffffffu, sf[mt][kk][1], L0);
                float x10 = __shfl_sync(0xffffffffu, sf[mt][kk][2], L0);
                float x11 = __shfl_sync(0xffffffffu, sf[mt][kk][3], L0);
                float y00 = __shfl_sync(0xffffffffu, sf[mt][kk][0], L2);
                float y01 = __shfl_sync(0xffffffffu, sf[mt][kk][1], L2);
                float y10 = __shfl_sync(0xffffffffu, sf[mt][kk][2], L2);
                float y11 = __shfl_sync(0xffffffffu, sf[mt][kk][3], L2);
                ap[mt][0] = f2tf(odd ? x01 : x00);
                ap[mt][1] = f2tf(odd ? x11 : x10);
                ap[mt][2] = f2tf(odd ? y01 : y00);
                ap[mt][3] = f2tf(odd ? y11 : y10);
            }
            #pragma unroll
            for (int nt = 0; nt < 8; nt++) {
                unsigned bf2[2];
                bf2[0] = __float_as_uint(Vb[(kk * 8 + tg    ) * VS_STRIDE + nt * 8 + g]);
                bf2[1] = __float_as_uint(Vb[(kk * 8 + tg + 4) * VS_STRIDE + nt * 8 + g]);
                #pragma unroll
                for (int mt = 0; mt < 2; mt++)
                    mma8(o[mt][nt], ap[mt], bf2);
            }
        }
    }

    // normalize and write to g_y [B,T,C], pre-rounded for the proj GEMM
    #pragma unroll
    for (int mt = 0; mt < 2; mt++) {
        float il0 = 1.0f / l_[mt][0], il1 = 1.0f / l_[mt][1];
        int t0 = qbase + w * 32 + mt * 16 + g;
        #pragma unroll
        for (int nt = 0; nt < 8; nt++) {
            int c = h * 64 + nt * 8 + 2 * tg;
            g_y[(b * T_ + t0    ) * C_ + c    ] = f2tff(o[mt][nt][0] * il0);
            g_y[(b * T_ + t0    ) * C_ + c + 1] = f2tff(o[mt][nt][1] * il0);
            g_y[(b * T_ + t0 + 8) * C_ + c    ] = f2tff(o[mt][nt][2] * il1);
            g_y[(b * T_ + t0 + 8) * C_ + c + 1] = f2tff(o[mt][nt][3] * il1);
        }
    }
}

// ---------------------------------------------------------------------------
extern "C" void kernel_launch(void* const* d_in, const int* in_sizes, int n_in,
                              void* d_out, int out_size)
{
    const float* x      = (const float*)d_in[0];
    const float* W_attn = (const float*)d_in[1];
    const float* b_attn = (const float*)d_in[2];
    const float* W_proj = (const float*)d_in[3];
    const float* b_proj = (const float*)d_in[4];
    float* out = (float*)d_out;

    cudaFuncSetAttribute(gemm_kernel,
                         cudaFuncAttributeMaxDynamicSharedMemorySize,
                         GEMM_SMEM_BYTES);
    cudaFuncSetAttribute(flash_kernel,
                         cudaFuncAttributeMaxDynamicSharedMemorySize,
                         FLASH_SMEM_BYTES);

    float *p_x, *p_wa, *p_wp;
    cudaGetSymbolAddress((void**)&p_x,  g_x);
    cudaGetSymbolAddress((void**)&p_wa, g_wa);
    cudaGetSymbolAddress((void**)&p_wp, g_wp);

    // 0) one-time TF32 pre-rounding of all GEMM operands (single launch)
    round_all_kernel<<<2048, 256>>>(
        (const float4*)x, (const float4*)W_attn, (const float4*)W_proj,
        (float4*)p_x, (float4*)p_wa, (float4*)p_wp);

    // 1) QKV projection + scatter into [B,H,T,D] (TF32-rounded)
    gemm_kernel<<<dim3((3 * C_) / 128, MROWS / 128), 256, GEMM_SMEM_BYTES>>>(
        b_attn, nullptr, MROWS, 3 * C_, C_, 0);

    // 2) causal flash attention -> g_y (qtile=256, warp tile 32x64, LPT)
    flash_kernel<<<dim3(T_ / 256, H_, B_), 256, FLASH_SMEM_BYTES>>>();

    // 3) output projection -> d_out
    gemm_kernel<<<dim3(C_ / 128, MROWS / 128), 256, GEMM_SMEM_BYTES>>>(
        b_proj, out, MROWS, C_, C_, 1);
}